// round 13
// baseline (speedup 1.0000x reference)
#include <cuda_runtime.h>
#include <cstdint>

// Kohonen SOM pairwise L2 distance via tf32 mma.sync.m16n8k8.
//   out[b][n] = sqrt(max(||x_b||^2 + ||w_n||^2 - 2 x_b.w_n, 0))
// x [B=65536,32] f32, w [N=4900,32] f32, out [B,N] f32.
//
// R13 = R12 (128x128 CTA tile, 512 threads, 4x4 warp grid, pitch-36 smem,
// cp.async fill, prologue norm kernel) with a BULK-COPY EPILOGUE:
// finals are staged in smem (reusing the dead operand tiles, 64 rows x
// pitch-144 floats, conflict-free STS.128) and drained by 64 per-row
// cp.async.bulk S->G copies of 512 B each. This removes the 1024
// half-empty STG wavefronts per CTA (row-scattered fragment stores) that
// have been the dominant L1 term since R3; smem stores have no sector
// penalty and the bulk engine writes fully-coalesced 512 B chunks.

#define BM 128
#define BN 128
#define KD 32
#define SP 36       // operand pitch (floats); (36r+c)%32 == (4r+c)%32
#define OP 144      // stage pitch (floats); 144%32==16 -> STS.128 conflict-free

#define SIDX(row, col) ((row) * SP + (col))

__device__ float g_x2[65536];
__device__ float g_w2[8192];

__device__ __forceinline__ float fsqrt_approx(float a) {
    float r;
    asm("sqrt.approx.f32 %0, %1;" : "=f"(r) : "f"(a));
    return r;
}

__device__ __forceinline__ unsigned smem_u32(const void* p) {
    unsigned a;
    asm("{ .reg .u64 t; cvta.to.shared.u64 t, %1; cvt.u32.u64 %0, t; }"
        : "=r"(a) : "l"(p));
    return a;
}

__device__ __forceinline__ void cp16(unsigned saddr, const void* gaddr) {
    asm volatile("cp.async.cg.shared.global [%0], [%1], 16;"
                 :: "r"(saddr), "l"(gaddr));
}
__device__ __forceinline__ void cp16_pred(unsigned saddr, const void* gaddr, int sz) {
    asm volatile("cp.async.cg.shared.global [%0], [%1], 16, %2;"
                 :: "r"(saddr), "l"(gaddr), "r"(sz));
}

__device__ __forceinline__ void mma_tf32(float* c, const unsigned* a, const unsigned* b) {
    asm volatile(
        "mma.sync.aligned.m16n8k8.row.col.f32.tf32.tf32.f32 "
        "{%0,%1,%2,%3}, {%4,%5,%6,%7}, {%8,%9}, {%0,%1,%2,%3};"
        : "+f"(c[0]), "+f"(c[1]), "+f"(c[2]), "+f"(c[3])
        : "r"(a[0]), "r"(a[1]), "r"(a[2]), "r"(a[3]),
          "r"(b[0]), "r"(b[1]));
}

// ---- prologue: row norms ----
__global__ void norms_kernel(const float* __restrict__ x,
                             const float* __restrict__ w,
                             int B, int N) {
    int i = blockIdx.x * 256 + threadIdx.x;
    if (i < B) {
        const float4* s = (const float4*)(x + (size_t)i * KD);
        float n = 0.f;
        #pragma unroll
        for (int q = 0; q < 8; ++q) {
            float4 v = s[q];
            n = fmaf(v.x, v.x, n); n = fmaf(v.y, v.y, n);
            n = fmaf(v.z, v.z, n); n = fmaf(v.w, v.w, n);
        }
        g_x2[i] = n;
    }
    if (i < N) {
        const float4* s = (const float4*)(w + (size_t)i * KD);
        float n = 0.f;
        #pragma unroll
        for (int q = 0; q < 8; ++q) {
            float4 v = s[q];
            n = fmaf(v.x, v.x, n); n = fmaf(v.y, v.y, n);
            n = fmaf(v.z, v.z, n); n = fmaf(v.w, v.w, n);
        }
        g_w2[i] = n;
    }
}

__global__ __launch_bounds__(512, 2)
void som_mma_kernel(const float* __restrict__ x,
                    const float* __restrict__ w,
                    float* __restrict__ out,
                    int B, int N) {
    __shared__ float sm[2 * BM * SP];   // 36864 B: operands, then stage (64xOP)
    float* As = sm;
    float* Bs = sm + BM * SP;
    float* stage = sm;                  // 64 * 144 * 4 = 36864 B, exact overlay

    const int tid    = threadIdx.x;
    const int m_base = blockIdx.y * BM;
    const int n_base = blockIdx.x * BN;

    // ---- fill: 2048 float4s via cp.async, 4 per thread ----
    {
        const unsigned as_base = smem_u32(As);
        const unsigned bs_base = smem_u32(Bs);
        #pragma unroll
        for (int p = 0; p < 4; ++p) {
            const int idx = tid + p * 512;       // float4 index, 0..2047
            const int row = (idx >> 3) & 127;
            const int q4  = (idx & 7) << 2;
            if (idx < 1024) {
                cp16(as_base + SIDX(row, q4) * 4,
                     x + (size_t)(m_base + row) * KD + q4);
            } else {
                const int gn = n_base + row;
                const int sz = (gn < N) ? 16 : 0;
                cp16_pred(bs_base + SIDX(row, q4) * 4,
                          w + (size_t)gn * KD + q4, sz);
            }
        }
        asm volatile("cp.async.commit_group;");
        asm volatile("cp.async.wait_group 0;");
    }
    __syncthreads();

    // ---- 4x4 warp grid, 32x32 warp tile, permuted B-fragment columns ----
    const int lane   = tid & 31;
    const int wid    = tid >> 5;
    const int warp_m = (wid & 3) * 32;
    const int warp_n = (wid >> 2) * 32;
    const int qr     = lane >> 2;
    const int qc     = lane & 3;

    const int pq = (qr >> 1) * 4 + (qr & 1);

    const float* a_row0 = &As[SIDX(warp_m + qr, qc)];
    const float* b_row0 = &Bs[SIDX(warp_n + pq, qc)];

    float acc[2][4][4];
    #pragma unroll
    for (int i = 0; i < 2; ++i)
        #pragma unroll
        for (int j = 0; j < 4; ++j)
            #pragma unroll
            for (int v = 0; v < 4; ++v) acc[i][j][v] = 0.f;

    #pragma unroll
    for (int ks = 0; ks < 4; ++ks) {
        const int k0 = ks * 8;

        unsigned af[2][4];
        #pragma unroll
        for (int tm = 0; tm < 2; ++tm) {
            const float* r0 = a_row0 + tm * 16 * SP;
            af[tm][0] = __float_as_uint(r0[k0]);
            af[tm][1] = __float_as_uint(r0[8 * SP + k0]);
            af[tm][2] = __float_as_uint(r0[k0 + 4]);
            af[tm][3] = __float_as_uint(r0[8 * SP + k0 + 4]);
        }

        unsigned bf[4][2];
        #pragma unroll
        for (int tn = 0; tn < 4; ++tn) {
            const float* c0 = b_row0 + ((tn >> 1) * 16 + (tn & 1) * 2) * SP;
            bf[tn][0] = __float_as_uint(c0[k0]);
            bf[tn][1] = __float_as_uint(c0[k0 + 4]);
        }

        #pragma unroll
        for (int tm = 0; tm < 2; ++tm)
            #pragma unroll
            for (int tn = 0; tn < 4; ++tn)
                mma_tf32(acc[tm][tn], af[tm], bf[tn]);
    }

    __syncthreads();   // operand tiles dead; stage overlay may be written

    // ---- staged bulk epilogue: 2 passes of 64 rows ----
    const int warp_pass = warp_m >> 6;                 // 0: wm 0/32, 1: wm 64/96
    const unsigned stage_base = smem_u32(stage);
    const int copy_bytes = (min(BN, N - n_base)) * 4;  // 512 or 144, mult of 16

    #pragma unroll
    for (int pass = 0; pass < 2; ++pass) {
        if (warp_pass == pass) {
            const int sm0 = warp_m & 63;
            #pragma unroll
            for (int tm = 0; tm < 2; ++tm) {
                const int s_lo = sm0 + tm * 16 + qr;       // stage rows
                const int r_lo = warp_m + tm * 16 + qr;    // tile rows
                const float x2_lo = __ldg(&g_x2[m_base + r_lo]);
                const float x2_hi = __ldg(&g_x2[m_base + r_lo + 8]);

                #pragma unroll
                for (int i = 0; i < 2; ++i) {
                    const int c  = warp_n + qc * 4 + i * 16;
                    const int gn = n_base + c;
                    if (gn < N) {
                        const float4 w2v = __ldg((const float4*)&g_w2[gn]);
                        const float* a0 = acc[tm][2 * i];
                        const float* a1 = acc[tm][2 * i + 1];

                        float4 lo, hi;
                        lo.x = fsqrt_approx(fmaxf(fmaf(-2.f, a0[0], x2_lo + w2v.x), 0.f));
                        lo.y = fsqrt_approx(fmaxf(fmaf(-2.f, a0[1], x2_lo + w2v.y), 0.f));
                        lo.z = fsqrt_approx(fmaxf(fmaf(-2.f, a1[0], x2_lo + w2v.z), 0.f));
                        lo.w = fsqrt_approx(fmaxf(fmaf(-2.f, a1[1], x2_lo + w2v.w), 0.f));
                        hi.x = fsqrt_approx(fmaxf(fmaf(-2.f, a0[2], x2_hi + w2v.x), 0.f));
                        hi.y = fsqrt_approx(fmaxf(fmaf(-2.f, a0[3], x2_hi + w2v.y), 0.f));
                        hi.z = fsqrt_approx(fmaxf(fmaf(-2.f, a1[2], x2_hi + w2v.z), 0.f));
                        hi.w = fsqrt_approx(fmaxf(fmaf(-2.f, a1[3], x2_hi + w2v.w), 0.f));

                        *(float4*)&stage[(s_lo    ) * OP + c] = lo;
                        *(float4*)&stage[(s_lo + 8) * OP + c] = hi;
                    }
                }
            }
        }
        __syncthreads();

        if (tid < 64) {
            asm volatile("fence.proxy.async.shared::cta;" ::: "memory");
            const int gm = m_base + pass * 64 + tid;
            float* dst = out + (size_t)gm * N + n_base;
            asm volatile(
                "cp.async.bulk.global.shared::cta.bulk_group [%0], [%1], %2;"
                :: "l"(dst), "r"(stage_base + tid * (OP * 4)), "r"(copy_bytes)
                : "memory");
            asm volatile("cp.async.bulk.commit_group;");
        }

        if (pass == 0) {
            if (tid < 64) {
                asm volatile("cp.async.bulk.wait_group.read 0;");
            }
            __syncthreads();   // stage readable -> pass 1 may overwrite
        }
    }

    if (tid < 64) {
        asm volatile("cp.async.bulk.wait_group 0;");
    }
}

extern "C" void kernel_launch(void* const* d_in, const int* in_sizes, int n_in,
                              void* d_out, int out_size) {
    const float* x = (const float*)d_in[0];
    const float* w = (const float*)d_in[1];
    float* out     = (float*)d_out;

    int B = in_sizes[0] / KD;   // 65536
    int N = in_sizes[1] / KD;   // 4900

    norms_kernel<<<(B + 255) / 256, 256>>>(x, w, B, N);

    dim3 grid((N + BN - 1) / BN, (B + BM - 1) / BM);
    som_mma_kernel<<<grid, 512>>>(x, w, out, B, N);
}

// round 14
// speedup vs baseline: 1.8815x; 1.8815x over previous
#include <cuda_runtime.h>
#include <cuda_bf16.h>
#include <cstdint>

// Kohonen SOM pairwise L2 distance via bf16 mma.sync.m16n8k16.
//   out[b][n] = sqrt(max(||x_b||^2 + ||w_n||^2 - 2 x_b.w_n, 0))
// x [B=65536,32] f32, w [N=4900,32] f32, out [B,N] f32.
//
// R14 = R12's machinery (cp.async fill, prologue kernel, global norms,
// 128x128 tile, 512 threads, 4x4 warp grid, STG.128 permuted epilogue)
// with bf16 OPERANDS PRE-CONVERTED IN THE PROLOGUE into device globals.
// Main-kernel fill is pure cp.async of bf16 (half the bytes, no CVT/STS —
// the two defects that sank R11). Mainloop LDS wavefronts and MMA count
// halve. B rows stored under the sigma placement (R11, correctness-proven)
// so fragment reads stay the plain {qr,qr+8} pattern; pitch 20 b32 makes
// every mainloop LDS bank-conflict-free (20r mod 32 = distinct mult of 4).

#define BM 128
#define BN 128
#define KD 32
#define PW 20        // b32 pitch per row (16 data + 4 pad); 80 B/row

__device__ float    g_x2[65536];
__device__ float    g_w2[8192];
__device__ unsigned g_xb[65536 * 16];   // bf16x2-packed x, 4 MB
__device__ unsigned g_wb[8192 * 16];    // bf16x2-packed w, 512 KB

__device__ __forceinline__ int sig16(int c) {
    return (((c >> 1) & 1) << 3) + ((c >> 2) << 1) + (c & 1);
}

__device__ __forceinline__ unsigned pack_bf16(float lo, float hi) {
    unsigned r;
    asm("cvt.rn.bf16x2.f32 %0, %1, %2;" : "=r"(r) : "f"(hi), "f"(lo));
    return r;
}

__device__ __forceinline__ float fsqrt_approx(float a) {
    float r;
    asm("sqrt.approx.f32 %0, %1;" : "=f"(r) : "f"(a));
    return r;
}

__device__ __forceinline__ unsigned smem_u32(const void* p) {
    unsigned a;
    asm("{ .reg .u64 t; cvta.to.shared.u64 t, %1; cvt.u32.u64 %0, t; }"
        : "=r"(a) : "l"(p));
    return a;
}

__device__ __forceinline__ void cp16(unsigned saddr, const void* gaddr) {
    asm volatile("cp.async.cg.shared.global [%0], [%1], 16;"
                 :: "r"(saddr), "l"(gaddr));
}
__device__ __forceinline__ void cp16_pred(unsigned saddr, const void* gaddr, int sz) {
    asm volatile("cp.async.cg.shared.global [%0], [%1], 16, %2;"
                 :: "r"(saddr), "l"(gaddr), "r"(sz));
}

__device__ __forceinline__ void mma_bf16(float* c, const unsigned* a, const unsigned* b) {
    asm volatile(
        "mma.sync.aligned.m16n8k16.row.col.f32.bf16.bf16.f32 "
        "{%0,%1,%2,%3}, {%4,%5,%6,%7}, {%8,%9}, {%0,%1,%2,%3};"
        : "+f"(c[0]), "+f"(c[1]), "+f"(c[2]), "+f"(c[3])
        : "r"(a[0]), "r"(a[1]), "r"(a[2]), "r"(a[3]),
          "r"(b[0]), "r"(b[1]));
}

// ---- prologue: norms + bf16 conversion ----
__global__ void prep_kernel(const float* __restrict__ x,
                            const float* __restrict__ w,
                            int B, int N) {
    int i = blockIdx.x * 256 + threadIdx.x;
    if (i < B) {
        const float4* s = (const float4*)(x + (size_t)i * KD);
        unsigned pk[16];
        float n = 0.f;
        #pragma unroll
        for (int q = 0; q < 8; ++q) {
            float4 v = s[q];
            n = fmaf(v.x, v.x, n); n = fmaf(v.y, v.y, n);
            n = fmaf(v.z, v.z, n); n = fmaf(v.w, v.w, n);
            pk[2 * q]     = pack_bf16(v.x, v.y);
            pk[2 * q + 1] = pack_bf16(v.z, v.w);
        }
        g_x2[i] = n;
        uint4* dst = (uint4*)&g_xb[i * 16];
        #pragma unroll
        for (int q = 0; q < 4; ++q)
            dst[q] = make_uint4(pk[4 * q], pk[4 * q + 1], pk[4 * q + 2], pk[4 * q + 3]);
    }
    if (i < N) {
        const float4* s = (const float4*)(w + (size_t)i * KD);
        unsigned pk[16];
        float n = 0.f;
        #pragma unroll
        for (int q = 0; q < 8; ++q) {
            float4 v = s[q];
            n = fmaf(v.x, v.x, n); n = fmaf(v.y, v.y, n);
            n = fmaf(v.z, v.z, n); n = fmaf(v.w, v.w, n);
            pk[2 * q]     = pack_bf16(v.x, v.y);
            pk[2 * q + 1] = pack_bf16(v.z, v.w);
        }
        g_w2[i] = n;
        uint4* dst = (uint4*)&g_wb[i * 16];
        #pragma unroll
        for (int q = 0; q < 4; ++q)
            dst[q] = make_uint4(pk[4 * q], pk[4 * q + 1], pk[4 * q + 2], pk[4 * q + 3]);
    }
}

__global__ __launch_bounds__(512, 2)
void som_mma_kernel(float* __restrict__ out, int B, int N) {
    __shared__ unsigned As[BM * PW];   // 10 KB
    __shared__ unsigned Bs[BN * PW];   // 10 KB (sigma-placed rows)

    const int tid    = threadIdx.x;
    const int m_base = blockIdx.y * BM;
    const int n_base = blockIdx.x * BN;

    // ---- fill: 1024 x 16B chunks via cp.async, 2 per thread ----
    {
        const unsigned as_base = smem_u32(As);
        const unsigned bs_base = smem_u32(Bs);
        #pragma unroll
        for (int p = 0; p < 2; ++p) {
            const int idx = tid + p * 512;     // 0..1023
            const int ch  = idx & 3;           // 16B chunk within row
            if (idx < 512) {
                const int row = idx >> 2;
                cp16(as_base + row * (PW * 4) + ch * 16,
                     (const char*)g_xb + ((size_t)(m_base + row) * 16 + ch * 4) * 4);
            } else {
                const int brow = (idx - 512) >> 2;
                const int srow = (brow & ~15) | sig16(brow & 15);
                const int gn   = n_base + brow;
                const int sz   = (gn < N) ? 16 : 0;   // 0 -> zero-fill, no read
                cp16_pred(bs_base + srow * (PW * 4) + ch * 16,
                          (const char*)g_wb + ((size_t)gn * 16 + ch * 4) * 4, sz);
            }
        }
        asm volatile("cp.async.commit_group;");
        asm volatile("cp.async.wait_group 0;");
    }
    __syncthreads();

    // ---- 4x4 warp grid, 32x32 warp tile, 2 k16 steps ----
    const int lane   = tid & 31;
    const int wid    = tid >> 5;
    const int warp_m = (wid & 3) * 32;
    const int warp_n = (wid >> 2) * 32;
    const int qr     = lane >> 2;
    const int qc     = lane & 3;

    const unsigned* a_base = &As[(warp_m + qr) * PW + qc];
    const unsigned* b_base = &Bs[(warp_n + qr) * PW + qc];

    float acc[2][4][4];
    #pragma unroll
    for (int i = 0; i < 2; ++i)
        #pragma unroll
        for (int j = 0; j < 4; ++j)
            #pragma unroll
            for (int v = 0; v < 4; ++v) acc[i][j][v] = 0.f;

    #pragma unroll
    for (int ks = 0; ks < 2; ++ks) {
        const int o = ks * 8;                  // b32 offset of this k16 chunk

        unsigned af[2][4];
        #pragma unroll
        for (int tm = 0; tm < 2; ++tm) {
            const unsigned* r0 = a_base + tm * 16 * PW;
            af[tm][0] = r0[o];
            af[tm][1] = r0[8 * PW + o];
            af[tm][2] = r0[o + 4];
            af[tm][3] = r0[8 * PW + o + 4];
        }

        unsigned bf[4][2];
        #pragma unroll
        for (int tn = 0; tn < 4; ++tn) {
            const unsigned* c0 = b_base + ((tn >> 1) * 16 + (tn & 1) * 8) * PW;
            bf[tn][0] = c0[o];
            bf[tn][1] = c0[o + 4];
        }

        #pragma unroll
        for (int tm = 0; tm < 2; ++tm)
            #pragma unroll
            for (int tn = 0; tn < 4; ++tn)
                mma_bf16(acc[tm][tn], af[tm], bf[tn]);
    }

    // ---- epilogue: norms from L2-hot globals; STG.128 per 4-col group ----
    #pragma unroll
    for (int tm = 0; tm < 2; ++tm) {
        const int r_lo = warp_m + tm * 16 + qr;
        const float x2_lo = __ldg(&g_x2[m_base + r_lo]);
        const float x2_hi = __ldg(&g_x2[m_base + r_lo + 8]);
        const size_t off_lo = (size_t)(m_base + r_lo) * N;
        const size_t off_hi = off_lo + (size_t)8 * N;

        #pragma unroll
        for (int i = 0; i < 2; ++i) {
            const int c  = warp_n + qc * 4 + i * 16;
            const int gn = n_base + c;
            if (gn < N) {                          // N%4==0 -> gn+3 valid
                const float4 w2v = __ldg((const float4*)&g_w2[gn]);
                const float* a0 = acc[tm][2 * i];      // cols gn, gn+1
                const float* a1 = acc[tm][2 * i + 1];  // cols gn+2, gn+3

                float4 lo, hi;
                lo.x = fsqrt_approx(fmaxf(fmaf(-2.f, a0[0], x2_lo + w2v.x), 0.f));
                lo.y = fsqrt_approx(fmaxf(fmaf(-2.f, a0[1], x2_lo + w2v.y), 0.f));
                lo.z = fsqrt_approx(fmaxf(fmaf(-2.f, a1[0], x2_lo + w2v.z), 0.f));
                lo.w = fsqrt_approx(fmaxf(fmaf(-2.f, a1[1], x2_lo + w2v.w), 0.f));
                hi.x = fsqrt_approx(fmaxf(fmaf(-2.f, a0[2], x2_hi + w2v.x), 0.f));
                hi.y = fsqrt_approx(fmaxf(fmaf(-2.f, a0[3], x2_hi + w2v.y), 0.f));
                hi.z = fsqrt_approx(fmaxf(fmaf(-2.f, a1[2], x2_hi + w2v.z), 0.f));
                hi.w = fsqrt_approx(fmaxf(fmaf(-2.f, a1[3], x2_hi + w2v.w), 0.f));

                __stcs((float4*)(out + off_lo + gn), lo);
                __stcs((float4*)(out + off_hi + gn), hi);
            }
        }
    }
}

extern "C" void kernel_launch(void* const* d_in, const int* in_sizes, int n_in,
                              void* d_out, int out_size) {
    const float* x = (const float*)d_in[0];
    const float* w = (const float*)d_in[1];
    float* out     = (float*)d_out;

    int B = in_sizes[0] / KD;   // 65536
    int N = in_sizes[1] / KD;   // 4900

    prep_kernel<<<(B + 255) / 256, 256>>>(x, w, B, N);

    dim3 grid((N + BN - 1) / BN, (B + BM - 1) / BM);
    som_mma_kernel<<<grid, 512>>>(out, B, N);
}